// round 14
// baseline (speedup 1.0000x reference)
#include <cuda_runtime.h>
#include <cuda_fp16.h>
#include <math.h>
#include <stdint.h>

// Problem dims (fixed by the reference)
#define Bb 4
#define Tt 2048
#define Hh 1024
#define Nn 16
#define CHUNKS 32
#define Lchunk (Tt / CHUNKS)   // 64
#define Mrows (Bb * Tt)        // 8192
#define Kd Hh                  // 1024 (plain fp16 GEMM K)

// ---------------- scratch (module-scope device memory) ----------------
__device__ __half g_Ah[(size_t)Mrows * Kd];               // x in fp16   16MB
__device__ __half g_Bh[(size_t)Hh * Kd];                  // W in fp16    2MB
__device__ __half g_dth[(size_t)Mrows * Hh];              // dt fp16     16MB
__device__ float g_q[(size_t)Bb * CHUNKS * Nn * Hh];      // q~  8MB
__device__ float g_S[(size_t)Bb * CHUNKS * Hh];           // 0.5MB
__device__ __half g_sinith[(size_t)Bb * CHUNKS * Nn * Hh]; // sinit~ fp16 4MB

__device__ __forceinline__ float ex2f(float x) {
    float y;
    asm("ex2.approx.ftz.f32 %0, %1;" : "=f"(y) : "f"(x));
    return y;
}
// half2 exp2: one MUFU op for two lanes, result stays half2 (y path only).
__device__ __forceinline__ __half2 h2ex2(__half2 a) {
    uint32_t r = *(uint32_t*)&a;
    asm("ex2.approx.f16x2 %0, %0;" : "+r"(r));
    return *(__half2*)&r;
}
__device__ __forceinline__ float softplusf(float z) {
    float az = fabsf(z);
    return fmaxf(z, 0.0f) + log1pf(__expf(-az));
}
__device__ __forceinline__ void cp_async16(uint32_t saddr, const void* gptr) {
    asm volatile("cp.async.cg.shared.global [%0], [%1], 16;"
                 :: "r"(saddr), "l"(__cvta_generic_to_global(gptr)) : "memory");
}
__device__ __forceinline__ void ldmatrix_x4(uint32_t* r, uint32_t saddr) {
    asm volatile("ldmatrix.sync.aligned.m8n8.x4.shared.b16 {%0,%1,%2,%3}, [%4];"
                 : "=r"(r[0]), "=r"(r[1]), "=r"(r[2]), "=r"(r[3]) : "r"(saddr));
}
__device__ __forceinline__ void mma16816(float* c, const uint32_t* a, uint32_t b0, uint32_t b1) {
    asm volatile(
        "mma.sync.aligned.m16n8k16.row.col.f32.f16.f16.f32 "
        "{%0,%1,%2,%3}, {%4,%5,%6,%7}, {%8,%9}, {%0,%1,%2,%3};"
        : "+f"(c[0]), "+f"(c[1]), "+f"(c[2]), "+f"(c[3])
        : "r"(a[0]), "r"(a[1]), "r"(a[2]), "r"(a[3]), "r"(b0), "r"(b1));
}

// ---------------------------------------------------------------------------
// fp32 -> fp16 conversion, x and W merged into ONE launch.
// ---------------------------------------------------------------------------
#define XB ((Mrows * Hh / 4) / 256)   // 8192
#define WB ((Hh * Hh / 4) / 256)      // 1024

__global__ __launch_bounds__(256)
void convert_kernel(const float* __restrict__ x, const float* __restrict__ W) {
    const int bb = blockIdx.x;
    const float* src;
    __half* dst;
    size_t i;
    if (bb < XB) {
        i = (size_t)bb * 256 + threadIdx.x;
        src = x; dst = g_Ah;
    } else {
        i = (size_t)(bb - XB) * 256 + threadIdx.x;
        src = W; dst = g_Bh;
    }
    float4 v = ((const float4*)src)[i];
    uint2 hi;
    hi.x = ((uint32_t)__half_as_ushort(__float2half_rn(v.y)) << 16) |
           __half_as_ushort(__float2half_rn(v.x));
    hi.y = ((uint32_t)__half_as_ushort(__float2half_rn(v.w)) << 16) |
           __half_as_ushort(__float2half_rn(v.z));
    *(uint2*)(dst + i * 4) = hi;
}

// ---------------------------------------------------------------------------
// mma.sync fp16 GEMM: dt = softplus(x @ W^T + b) -> g_dth (fp16)
// ---------------------------------------------------------------------------
#define GBM 128
#define GBN 128
#define GBK 64
#define NKT (Kd / GBK)             // 16
#define NSTAGE 3
#define A_BYTES (GBM * GBK * 2)    // 16KB
#define STAGE_BYTES (2 * A_BYTES)  // 32KB (A + B)
#define GEMM_DYN_SMEM (NSTAGE * STAGE_BYTES)  // 96KB

__device__ __forceinline__ uint32_t swz64(int r, int c) {
    return (uint32_t)(r * 128 + ((c ^ (r & 7)) << 4));
}

__global__ __launch_bounds__(256, 2)
void gemm_mma_kernel(const float* __restrict__ bdt) {
    extern __shared__ __align__(16) char dsm[];

    const int tid = threadIdx.x;
    const int wid = tid >> 5, lane = tid & 31;
    const int n0 = blockIdx.x * GBN;
    const int m0 = blockIdx.y * GBM;
    const int wm = (wid >> 2) * 64;
    const int wn = (wid & 3) * 32;

    const uint32_t s0 = (uint32_t)__cvta_generic_to_shared(dsm);

    const __half* Abase = g_Ah + (size_t)m0 * Kd;
    const __half* Bbase = g_Bh + (size_t)n0 * Kd;

    auto issue_loads = [&](int kt, int stage) {
        const uint32_t sA = s0 + stage * STAGE_BYTES;
        const uint32_t sB = sA + A_BYTES;
        const __half* Ag = Abase + kt * GBK;
        const __half* Bg = Bbase + kt * GBK;
#pragma unroll
        for (int i = 0; i < 4; i++) {
            int ch = tid + i * 256;            // 0..1023
            int r = ch >> 3, c = ch & 7;
            cp_async16(sA + swz64(r, c), Ag + (size_t)r * Kd + c * 8);
        }
#pragma unroll
        for (int i = 0; i < 4; i++) {
            int ch = tid + i * 256;
            int r = ch >> 3, c = ch & 7;
            cp_async16(sB + swz64(r, c), Bg + (size_t)r * Kd + c * 8);
        }
        asm volatile("cp.async.commit_group;" ::: "memory");
    };

    float acc[4][4][4];
#pragma unroll
    for (int i = 0; i < 4; i++)
#pragma unroll
        for (int j = 0; j < 4; j++)
#pragma unroll
            for (int k = 0; k < 4; k++) acc[i][j][k] = 0.0f;

    issue_loads(0, 0);
    issue_loads(1, 1);

    const int lrow = lane & 15;
    const int lkh  = (lane >> 4) & 1;

    int stage = 0;
    for (int kt = 0; kt < NKT; kt++) {
        asm volatile("cp.async.wait_group %0;" :: "n"(NSTAGE - 2) : "memory");
        __syncthreads();

        if (kt + NSTAGE - 1 < NKT) {
            int ns = stage + 2; if (ns >= NSTAGE) ns -= NSTAGE;
            issue_loads(kt + NSTAGE - 1, ns);
        } else {
            asm volatile("cp.async.commit_group;" ::: "memory");
        }

        const uint32_t sA = s0 + stage * STAGE_BYTES;
        const uint32_t sB = sA + A_BYTES;

#pragma unroll
        for (int ks = 0; ks < 4; ks++) {       // 4 x K=16
            const int c16 = ks * 2 + lkh;
            uint32_t a[4][4];
#pragma unroll
            for (int mb = 0; mb < 4; mb++)
                ldmatrix_x4(a[mb], sA + swz64(wm + mb * 16 + lrow, c16));
            uint32_t bf[2][4];
#pragma unroll
            for (int nb = 0; nb < 2; nb++)
                ldmatrix_x4(bf[nb], sB + swz64(wn + nb * 16 + lrow, c16));
#pragma unroll
            for (int mb = 0; mb < 4; mb++)
#pragma unroll
                for (int j = 0; j < 4; j++)
                    mma16816(acc[mb][j], a[mb], bf[j >> 1][j & 1], bf[j >> 1][(j & 1) + 2]);
        }
        if (++stage >= NSTAGE) stage = 0;
    }

    // Epilogue: bias + softplus; half2 stores to g_dth [m][h]
    const int g = lane >> 2;
    const int t = lane & 3;
#pragma unroll
    for (int j = 0; j < 4; j++) {
        const int h = n0 + wn + j * 8 + 2 * t;
        const float b0 = __ldg(&bdt[h]);
        const float b1 = __ldg(&bdt[h + 1]);
#pragma unroll
        for (int mb = 0; mb < 4; mb++) {
            const int m = m0 + wm + mb * 16 + g;
            *(half2*)(&g_dth[(size_t)m * Hh + h]) =
                __floats2half2_rn(softplusf(acc[mb][j][0] + b0),
                                  softplusf(acc[mb][j][1] + b1));
            *(half2*)(&g_dth[(size_t)(m + 8) * Hh + h]) =
                __floats2half2_rn(softplusf(acc[mb][j][2] + b0),
                                  softplusf(acc[mb][j][3] + b1));
        }
    }
}

// ---------------------------------------------------------------------------
// Scan phases. s~ = s / Bv transform. dt slab fp16 (32KB) + x slab fp32 (64KB).
// ---------------------------------------------------------------------------
#define XSLAB_FLOATS (Lchunk * 256)            // 16384 floats = 64KB
#define DSLAB_HALVES (Lchunk * 256)            // 16384 halves = 32KB
#define SLAB_BYTES_TOT (XSLAB_FLOATS * 4 + DSLAB_HALVES * 2)  // 96KB

__device__ __forceinline__ void stage_two_slabs(uint32_t sD, uint32_t sU,
                                                const __half* __restrict__ dsrc,
                                                const float* __restrict__ usrc,
                                                int tid) {
    // dt slab: 2048 x 16B chunks, rows of 512B
#pragma unroll
    for (int i = 0; i < 8; i++) {
        int ch = tid + i * 256;                // 0..2047
        int t = ch >> 5;
        int off = (ch & 31) << 4;
        cp_async16(sD + t * 512 + off, (const char*)(dsrc + (size_t)t * Hh) + off);
    }
    // x slab: 4096 x 16B chunks, rows of 1KB
#pragma unroll
    for (int i = 0; i < 16; i++) {
        int ch = tid + i * 256;                // 0..4095
        int t = ch >> 6;
        int off = (ch & 63) << 4;
        cp_async16(sU + t * 1024 + off, (const char*)(usrc + (size_t)t * Hh) + off);
    }
    asm volatile("cp.async.commit_group;" ::: "memory");
    asm volatile("cp.async.wait_group 0;" ::: "memory");
}

// ---------------------------------------------------------------------------
// Phase 1: state path — fp32 exp, fp32 state (feeds state_final via q).
// ---------------------------------------------------------------------------
__global__ __launch_bounds__(256)
void phase1_kernel(const float* __restrict__ x, const float* __restrict__ Alog) {
    extern __shared__ __align__(16) char sraw[];
    __half* slabD = (__half*)sraw;
    float* slabU = (float*)(sraw + DSLAB_HALVES * 2);
    const int tid = threadIdx.x;
    const int h0 = blockIdx.x * 256;
    const int h = h0 + tid;
    const int c = blockIdx.y;
    const int b = blockIdx.z;

    const uint32_t sD = (uint32_t)__cvta_generic_to_shared(slabD);
    const uint32_t sU = (uint32_t)__cvta_generic_to_shared(slabU);
    const size_t base = ((size_t)b * Tt + c * Lchunk) * Hh + h0;
    stage_two_slabs(sD, sU, g_dth + base, x + base, tid);

    float A2[Nn], s[Nn];
#pragma unroll
    for (int i = 0; i < 4; i++) {
        float4 av = *(const float4*)(Alog + h * Nn + i * 4);
        A2[i*4+0] = -expf(av.x) * 1.4426950408889634f;
        A2[i*4+1] = -expf(av.y) * 1.4426950408889634f;
        A2[i*4+2] = -expf(av.z) * 1.4426950408889634f;
        A2[i*4+3] = -expf(av.w) * 1.4426950408889634f;
    }
#pragma unroll
    for (int n = 0; n < Nn; ++n) s[n] = 0.0f;

    __syncthreads();

    float S = 0.0f;
#pragma unroll 8
    for (int tt = 0; tt < Lchunk; ++tt) {
        const float dtv = __half2float(slabD[tt * 256 + tid]);
        const float uv  = slabU[tt * 256 + tid];
        const float du  = dtv * uv;
        S += dtv;
#pragma unroll
        for (int n = 0; n < Nn; ++n) {
            const float e = ex2f(dtv * A2[n]);   // fp32: state path
            s[n] = fmaf(e, s[n], du);
        }
    }
#pragma unroll
    for (int n = 0; n < Nn; ++n)
        g_q[(((size_t)(b * CHUNKS + c)) * Nn + n) * Hh + h] = s[n];
    g_S[(size_t)(b * CHUNKS + c) * Hh + h] = S;
}

// ---------------------------------------------------------------------------
// Phase 2: sequential combine, deep batch prefetch (P2B=16 -> 2 latency stops)
// ---------------------------------------------------------------------------
#define P2B 16
__global__ __launch_bounds__(256)
void phase2_kernel(const float* __restrict__ Alog, const float* __restrict__ Bmat,
                   float* __restrict__ out, int write_state) {
    const int idx = blockIdx.x * 256 + threadIdx.x;
    const int h = idx & (Hh - 1);
    const int u = idx >> 10;
    const int n = u & (Nn - 1);
    const int b = u >> 4;

    const float A2 = -expf(Alog[h * Nn + n]) * 1.4426950408889634f;

    const float* qp = g_q + ((size_t)b * CHUNKS * Nn + n) * Hh + h;
    const float* Sp = g_S + (size_t)b * CHUNKS * Hh + h;
    __half* ip = g_sinith + ((size_t)b * CHUNKS * Nn + n) * Hh + h;

    float qv[P2B], Sv[P2B], qn[P2B], Sn[P2B];
#pragma unroll
    for (int i = 0; i < P2B; i++) {
        qv[i] = qp[(size_t)i * (Nn * Hh)];
        Sv[i] = Sp[(size_t)i * Hh];
    }

    float s = 0.0f;
    for (int cb = 0; cb < CHUNKS; cb += P2B) {
        if (cb + P2B < CHUNKS) {
#pragma unroll
            for (int i = 0; i < P2B; i++) {
                qn[i] = qp[(size_t)(cb + P2B + i) * (Nn * Hh)];
                Sn[i] = Sp[(size_t)(cb + P2B + i) * Hh];
            }
        }
#pragma unroll
        for (int i = 0; i < P2B; i++) {
            ip[(size_t)(cb + i) * (Nn * Hh)] = __float2half(s);
            const float e = ex2f(Sv[i] * A2);
            s = fmaf(e, s, qv[i]);
        }
#pragma unroll
        for (int i = 0; i < P2B; i++) { qv[i] = qn[i]; Sv[i] = Sn[i]; }
    }
    if (write_state) {
        out[(size_t)Mrows * Hh + ((size_t)b * Hh + h) * Nn + n] = s * Bmat[h * Nn + n];
    }
}

// ---------------------------------------------------------------------------
// Phase 3: y path — full half2 recurrence (C·s term small; D·u exact fp32).
// ---------------------------------------------------------------------------
__global__ __launch_bounds__(256)
void phase3_kernel(const float* __restrict__ x, const float* __restrict__ Alog,
                   const float* __restrict__ Bmat, const float* __restrict__ Cmat,
                   const float* __restrict__ Dvec, float* __restrict__ out) {
    extern __shared__ __align__(16) char sraw[];
    __half* slabD = (__half*)sraw;
    float* slabU = (float*)(sraw + DSLAB_HALVES * 2);
    const int tid = threadIdx.x;
    const int h0 = blockIdx.x * 256;
    const int h = h0 + tid;
    const int c = blockIdx.y;
    const int b = blockIdx.z;

    const uint32_t sD = (uint32_t)__cvta_generic_to_shared(slabD);
    const uint32_t sU = (uint32_t)__cvta_generic_to_shared(slabU);
    const size_t base = ((size_t)b * Tt + c * Lchunk) * Hh + h0;
    stage_two_slabs(sD, sU, g_dth + base, x + base, tid);

    __half2 A2h[Nn / 2], CBh[Nn / 2], s2[Nn / 2];
#pragma unroll
    for (int i = 0; i < 4; i++) {
        float4 av = *(const float4*)(Alog + h * Nn + i * 4);
        float4 bv = *(const float4*)(Bmat + h * Nn + i * 4);
        float4 cv = *(const float4*)(Cmat + h * Nn + i * 4);
        A2h[i*2]   = __floats2half2_rn(-expf(av.x) * 1.4426950408889634f,
                                       -expf(av.y) * 1.4426950408889634f);
        A2h[i*2+1] = __floats2half2_rn(-expf(av.z) * 1.4426950408889634f,
                                       -expf(av.w) * 1.4426950408889634f);
        CBh[i*2]   = __floats2half2_rn(bv.x * cv.x, bv.y * cv.y);
        CBh[i*2+1] = __floats2half2_rn(bv.z * cv.z, bv.w * cv.w);
    }
    {
        const __half* ip = g_sinith + ((size_t)(b * CHUNKS + c) * Nn) * Hh + h;
#pragma unroll
        for (int p = 0; p < Nn / 2; ++p)
            s2[p] = __halves2half2(ip[(size_t)(2*p) * Hh], ip[(size_t)(2*p+1) * Hh]);
    }

    const float Dh = Dvec[h];
    float* yp = out + base + tid;

    __syncthreads();

#pragma unroll 8
    for (int tt = 0; tt < Lchunk; ++tt) {
        const __half dth = slabD[tt * 256 + tid];
        const __half2 dt2 = __half2half2(dth);
        const float uv = slabU[tt * 256 + tid];
        const float du = __half2float(dth) * uv;
        const __half2 du2 = __float2half2_rn(du);
        __half2 y2 = __float2half2_rn(0.0f);
#pragma unroll
        for (int p = 0; p < Nn / 2; ++p) {
            const __half2 e2 = h2ex2(__hmul2(dt2, A2h[p]));
            s2[p] = __hfma2(e2, s2[p], du2);
            y2 = __hfma2(s2[p], CBh[p], y2);
        }
        yp[(size_t)tt * Hh] = fmaf(Dh, uv, __low2float(y2) + __high2float(y2));
    }
}

// ---------------------------------------------------------------------------
extern "C" void kernel_launch(void* const* d_in, const int* in_sizes, int n_in,
                              void* d_out, int out_size) {
    const float* x     = (const float*)d_in[0];
    const float* A_log = (const float*)d_in[1];
    const float* B_mat = (const float*)d_in[2];
    const float* C_mat = (const float*)d_in[3];
    const float* D_vec = (const float*)d_in[4];
    const float* W_dt  = (const float*)d_in[5];
    const float* b_dt  = (const float*)d_in[6];
    float* out = (float*)d_out;

    static int attr_set = 0;
    if (!attr_set) {
        cudaFuncSetAttribute(gemm_mma_kernel,
                             cudaFuncAttributeMaxDynamicSharedMemorySize, GEMM_DYN_SMEM);
        cudaFuncSetAttribute(phase1_kernel,
                             cudaFuncAttributeMaxDynamicSharedMemorySize, SLAB_BYTES_TOT);
        cudaFuncSetAttribute(phase3_kernel,
                             cudaFuncAttributeMaxDynamicSharedMemorySize, SLAB_BYTES_TOT);
        attr_set = 1;
    }

    // fp16 operand prep (x and W in one launch)
    convert_kernel<<<XB + WB, 256>>>(x, W_dt);

    // tensor-core GEMM + softplus epilogue -> g_dth (fp16)
    gemm_mma_kernel<<<dim3(Hh / GBN, Mrows / GBM), 256, GEMM_DYN_SMEM>>>(b_dt);

    // chunked scan (s~ space)
    phase1_kernel<<<dim3(Hh / 256, CHUNKS, Bb), 256, SLAB_BYTES_TOT>>>(x, A_log);

    const int write_state =
        ((size_t)out_size >= (size_t)Mrows * Hh + (size_t)Bb * Hh * Nn) ? 1 : 0;
    phase2_kernel<<<(Bb * Hh * Nn) / 256, 256>>>(A_log, B_mat, out, write_state);

    phase3_kernel<<<dim3(Hh / 256, CHUNKS, Bb), 256, SLAB_BYTES_TOT>>>(x, A_log, B_mat, C_mat, D_vec, out);
}

// round 15
// speedup vs baseline: 1.0505x; 1.0505x over previous
#include <cuda_runtime.h>
#include <cuda_fp16.h>
#include <math.h>
#include <stdint.h>

// Problem dims (fixed by the reference)
#define Bb 4
#define Tt 2048
#define Hh 1024
#define Nn 16
#define CHUNKS 64
#define Lchunk (Tt / CHUNKS)   // 32
#define Mrows (Bb * Tt)        // 8192
#define Kd Hh                  // 1024 (plain fp16 GEMM K)

// ---------------- scratch (module-scope device memory) ----------------
__device__ __half g_Ah[(size_t)Mrows * Kd];               // x in fp16   16MB
__device__ __half g_Bh[(size_t)Hh * Kd];                  // W in fp16    2MB
__device__ __half g_dth[(size_t)Mrows * Hh];              // dt fp16     16MB
__device__ float g_q[(size_t)Bb * CHUNKS * Nn * Hh];      // q~ 16MB
__device__ float g_S[(size_t)Bb * CHUNKS * Hh];           //  1MB
__device__ __half g_sinith[(size_t)Bb * CHUNKS * Nn * Hh]; // sinit~ fp16 8MB

__device__ __forceinline__ float ex2f(float x) {
    float y;
    asm("ex2.approx.ftz.f32 %0, %1;" : "=f"(y) : "f"(x));
    return y;
}
// half2 exp2: one MUFU op for two lanes, result stays half2 (y path only).
__device__ __forceinline__ __half2 h2ex2(__half2 a) {
    uint32_t r = *(uint32_t*)&a;
    asm("ex2.approx.f16x2 %0, %0;" : "+r"(r));
    return *(__half2*)&r;
}
__device__ __forceinline__ float softplusf(float z) {
    float az = fabsf(z);
    return fmaxf(z, 0.0f) + log1pf(__expf(-az));
}
__device__ __forceinline__ void cp_async16(uint32_t saddr, const void* gptr) {
    asm volatile("cp.async.cg.shared.global [%0], [%1], 16;"
                 :: "r"(saddr), "l"(__cvta_generic_to_global(gptr)) : "memory");
}
__device__ __forceinline__ void ldmatrix_x4(uint32_t* r, uint32_t saddr) {
    asm volatile("ldmatrix.sync.aligned.m8n8.x4.shared.b16 {%0,%1,%2,%3}, [%4];"
                 : "=r"(r[0]), "=r"(r[1]), "=r"(r[2]), "=r"(r[3]) : "r"(saddr));
}
__device__ __forceinline__ void mma16816(float* c, const uint32_t* a, uint32_t b0, uint32_t b1) {
    asm volatile(
        "mma.sync.aligned.m16n8k16.row.col.f32.f16.f16.f32 "
        "{%0,%1,%2,%3}, {%4,%5,%6,%7}, {%8,%9}, {%0,%1,%2,%3};"
        : "+f"(c[0]), "+f"(c[1]), "+f"(c[2]), "+f"(c[3])
        : "r"(a[0]), "r"(a[1]), "r"(a[2]), "r"(a[3]), "r"(b0), "r"(b1));
}

// ---------------------------------------------------------------------------
// fp32 -> fp16 conversion, x and W merged into ONE launch.
// ---------------------------------------------------------------------------
#define XB ((Mrows * Hh / 4) / 256)   // 8192
#define WB ((Hh * Hh / 4) / 256)      // 1024

__global__ __launch_bounds__(256)
void convert_kernel(const float* __restrict__ x, const float* __restrict__ W) {
    const int bb = blockIdx.x;
    const float* src;
    __half* dst;
    size_t i;
    if (bb < XB) {
        i = (size_t)bb * 256 + threadIdx.x;
        src = x; dst = g_Ah;
    } else {
        i = (size_t)(bb - XB) * 256 + threadIdx.x;
        src = W; dst = g_Bh;
    }
    float4 v = ((const float4*)src)[i];
    uint2 hi;
    hi.x = ((uint32_t)__half_as_ushort(__float2half_rn(v.y)) << 16) |
           __half_as_ushort(__float2half_rn(v.x));
    hi.y = ((uint32_t)__half_as_ushort(__float2half_rn(v.w)) << 16) |
           __half_as_ushort(__float2half_rn(v.z));
    *(uint2*)(dst + i * 4) = hi;
}

// ---------------------------------------------------------------------------
// mma.sync fp16 GEMM: dt = softplus(x @ W^T + b) -> g_dth (fp16)
// ---------------------------------------------------------------------------
#define GBM 128
#define GBN 128
#define GBK 64
#define NKT (Kd / GBK)             // 16
#define NSTAGE 3
#define A_BYTES (GBM * GBK * 2)    // 16KB
#define STAGE_BYTES (2 * A_BYTES)  // 32KB (A + B)
#define GEMM_DYN_SMEM (NSTAGE * STAGE_BYTES)  // 96KB

__device__ __forceinline__ uint32_t swz64(int r, int c) {
    return (uint32_t)(r * 128 + ((c ^ (r & 7)) << 4));
}

__global__ __launch_bounds__(256, 2)
void gemm_mma_kernel(const float* __restrict__ bdt) {
    extern __shared__ __align__(16) char dsm[];

    const int tid = threadIdx.x;
    const int wid = tid >> 5, lane = tid & 31;
    const int n0 = blockIdx.x * GBN;
    const int m0 = blockIdx.y * GBM;
    const int wm = (wid >> 2) * 64;
    const int wn = (wid & 3) * 32;

    const uint32_t s0 = (uint32_t)__cvta_generic_to_shared(dsm);

    const __half* Abase = g_Ah + (size_t)m0 * Kd;
    const __half* Bbase = g_Bh + (size_t)n0 * Kd;

    auto issue_loads = [&](int kt, int stage) {
        const uint32_t sA = s0 + stage * STAGE_BYTES;
        const uint32_t sB = sA + A_BYTES;
        const __half* Ag = Abase + kt * GBK;
        const __half* Bg = Bbase + kt * GBK;
#pragma unroll
        for (int i = 0; i < 4; i++) {
            int ch = tid + i * 256;            // 0..1023
            int r = ch >> 3, c = ch & 7;
            cp_async16(sA + swz64(r, c), Ag + (size_t)r * Kd + c * 8);
        }
#pragma unroll
        for (int i = 0; i < 4; i++) {
            int ch = tid + i * 256;
            int r = ch >> 3, c = ch & 7;
            cp_async16(sB + swz64(r, c), Bg + (size_t)r * Kd + c * 8);
        }
        asm volatile("cp.async.commit_group;" ::: "memory");
    };

    float acc[4][4][4];
#pragma unroll
    for (int i = 0; i < 4; i++)
#pragma unroll
        for (int j = 0; j < 4; j++)
#pragma unroll
            for (int k = 0; k < 4; k++) acc[i][j][k] = 0.0f;

    issue_loads(0, 0);
    issue_loads(1, 1);

    const int lrow = lane & 15;
    const int lkh  = (lane >> 4) & 1;

    int stage = 0;
    for (int kt = 0; kt < NKT; kt++) {
        asm volatile("cp.async.wait_group %0;" :: "n"(NSTAGE - 2) : "memory");
        __syncthreads();

        if (kt + NSTAGE - 1 < NKT) {
            int ns = stage + 2; if (ns >= NSTAGE) ns -= NSTAGE;
            issue_loads(kt + NSTAGE - 1, ns);
        } else {
            asm volatile("cp.async.commit_group;" ::: "memory");
        }

        const uint32_t sA = s0 + stage * STAGE_BYTES;
        const uint32_t sB = sA + A_BYTES;

#pragma unroll
        for (int ks = 0; ks < 4; ks++) {       // 4 x K=16
            const int c16 = ks * 2 + lkh;
            uint32_t a[4][4];
#pragma unroll
            for (int mb = 0; mb < 4; mb++)
                ldmatrix_x4(a[mb], sA + swz64(wm + mb * 16 + lrow, c16));
            uint32_t bf[2][4];
#pragma unroll
            for (int nb = 0; nb < 2; nb++)
                ldmatrix_x4(bf[nb], sB + swz64(wn + nb * 16 + lrow, c16));
#pragma unroll
            for (int mb = 0; mb < 4; mb++)
#pragma unroll
                for (int j = 0; j < 4; j++)
                    mma16816(acc[mb][j], a[mb], bf[j >> 1][j & 1], bf[j >> 1][(j & 1) + 2]);
        }
        if (++stage >= NSTAGE) stage = 0;
    }

    // Epilogue: bias + softplus; half2 stores to g_dth [m][h]
    const int g = lane >> 2;
    const int t = lane & 3;
#pragma unroll
    for (int j = 0; j < 4; j++) {
        const int h = n0 + wn + j * 8 + 2 * t;
        const float b0 = __ldg(&bdt[h]);
        const float b1 = __ldg(&bdt[h + 1]);
#pragma unroll
        for (int mb = 0; mb < 4; mb++) {
            const int m = m0 + wm + mb * 16 + g;
            *(half2*)(&g_dth[(size_t)m * Hh + h]) =
                __floats2half2_rn(softplusf(acc[mb][j][0] + b0),
                                  softplusf(acc[mb][j][1] + b1));
            *(half2*)(&g_dth[(size_t)(m + 8) * Hh + h]) =
                __floats2half2_rn(softplusf(acc[mb][j][2] + b0),
                                  softplusf(acc[mb][j][3] + b1));
        }
    }
}

// ---------------------------------------------------------------------------
// Scan phases. s~ = s / Bv transform. dt slab fp16 (16KB) + x slab fp32 (32KB).
// ---------------------------------------------------------------------------
#define XSLAB_FLOATS (Lchunk * 256)            // 8192 floats = 32KB
#define DSLAB_HALVES (Lchunk * 256)            // 8192 halves = 16KB
#define SLAB_BYTES_TOT (XSLAB_FLOATS * 4 + DSLAB_HALVES * 2)  // 48KB

__device__ __forceinline__ void stage_two_slabs(uint32_t sD, uint32_t sU,
                                                const __half* __restrict__ dsrc,
                                                const float* __restrict__ usrc,
                                                int tid) {
    // dt slab: 1024 x 16B chunks, rows of 512B
#pragma unroll
    for (int i = 0; i < 4; i++) {
        int ch = tid + i * 256;                // 0..1023
        int t = ch >> 5;
        int off = (ch & 31) << 4;
        cp_async16(sD + t * 512 + off, (const char*)(dsrc + (size_t)t * Hh) + off);
    }
    // x slab: 2048 x 16B chunks, rows of 1KB
#pragma unroll
    for (int i = 0; i < 8; i++) {
        int ch = tid + i * 256;                // 0..2047
        int t = ch >> 6;
        int off = (ch & 63) << 4;
        cp_async16(sU + t * 1024 + off, (const char*)(usrc + (size_t)t * Hh) + off);
    }
    asm volatile("cp.async.commit_group;" ::: "memory");
    asm volatile("cp.async.wait_group 0;" ::: "memory");
}

// ---------------------------------------------------------------------------
// Phase 1: state path — fp32 exp, fp32 state (feeds state_final via q).
// ---------------------------------------------------------------------------
__global__ __launch_bounds__(256)
void phase1_kernel(const float* __restrict__ x, const float* __restrict__ Alog) {
    extern __shared__ __align__(16) char sraw[];
    __half* slabD = (__half*)sraw;
    float* slabU = (float*)(sraw + DSLAB_HALVES * 2);
    const int tid = threadIdx.x;
    const int h0 = blockIdx.x * 256;
    const int h = h0 + tid;
    const int c = blockIdx.y;
    const int b = blockIdx.z;

    const uint32_t sD = (uint32_t)__cvta_generic_to_shared(slabD);
    const uint32_t sU = (uint32_t)__cvta_generic_to_shared(slabU);
    const size_t base = ((size_t)b * Tt + c * Lchunk) * Hh + h0;
    stage_two_slabs(sD, sU, g_dth + base, x + base, tid);

    float A2[Nn], s[Nn];
#pragma unroll
    for (int i = 0; i < 4; i++) {
        float4 av = *(const float4*)(Alog + h * Nn + i * 4);
        A2[i*4+0] = -expf(av.x) * 1.4426950408889634f;
        A2[i*4+1] = -expf(av.y) * 1.4426950408889634f;
        A2[i*4+2] = -expf(av.z) * 1.4426950408889634f;
        A2[i*4+3] = -expf(av.w) * 1.4426950408889634f;
    }
#pragma unroll
    for (int n = 0; n < Nn; ++n) s[n] = 0.0f;

    __syncthreads();

    float S = 0.0f;
#pragma unroll 8
    for (int tt = 0; tt < Lchunk; ++tt) {
        const float dtv = __half2float(slabD[tt * 256 + tid]);
        const float uv  = slabU[tt * 256 + tid];
        const float du  = dtv * uv;
        S += dtv;
#pragma unroll
        for (int n = 0; n < Nn; ++n) {
            const float e = ex2f(dtv * A2[n]);   // fp32: state path
            s[n] = fmaf(e, s[n], du);
        }
    }
#pragma unroll
    for (int n = 0; n < Nn; ++n)
        g_q[(((size_t)(b * CHUNKS + c)) * Nn + n) * Hh + h] = s[n];
    g_S[(size_t)(b * CHUNKS + c) * Hh + h] = S;
}

// ---------------------------------------------------------------------------
// Phase 2: sequential combine, deep batch prefetch (P2B=16 -> 4 latency stops)
// ---------------------------------------------------------------------------
#define P2B 16
__global__ __launch_bounds__(256)
void phase2_kernel(const float* __restrict__ Alog, const float* __restrict__ Bmat,
                   float* __restrict__ out, int write_state) {
    const int idx = blockIdx.x * 256 + threadIdx.x;
    const int h = idx & (Hh - 1);
    const int u = idx >> 10;
    const int n = u & (Nn - 1);
    const int b = u >> 4;

    const float A2 = -expf(Alog[h * Nn + n]) * 1.4426950408889634f;

    const float* qp = g_q + ((size_t)b * CHUNKS * Nn + n) * Hh + h;
    const float* Sp = g_S + (size_t)b * CHUNKS * Hh + h;
    __half* ip = g_sinith + ((size_t)b * CHUNKS * Nn + n) * Hh + h;

    float qv[P2B], Sv[P2B], qn[P2B], Sn[P2B];
#pragma unroll
    for (int i = 0; i < P2B; i++) {
        qv[i] = qp[(size_t)i * (Nn * Hh)];
        Sv[i] = Sp[(size_t)i * Hh];
    }

    float s = 0.0f;
    for (int cb = 0; cb < CHUNKS; cb += P2B) {
        if (cb + P2B < CHUNKS) {
#pragma unroll
            for (int i = 0; i < P2B; i++) {
                qn[i] = qp[(size_t)(cb + P2B + i) * (Nn * Hh)];
                Sn[i] = Sp[(size_t)(cb + P2B + i) * Hh];
            }
        }
#pragma unroll
        for (int i = 0; i < P2B; i++) {
            ip[(size_t)(cb + i) * (Nn * Hh)] = __float2half(s);
            const float e = ex2f(Sv[i] * A2);
            s = fmaf(e, s, qv[i]);
        }
#pragma unroll
        for (int i = 0; i < P2B; i++) { qv[i] = qn[i]; Sv[i] = Sn[i]; }
    }
    if (write_state) {
        out[(size_t)Mrows * Hh + ((size_t)b * Hh + h) * Nn + n] = s * Bmat[h * Nn + n];
    }
}

// ---------------------------------------------------------------------------
// Phase 3: y path — full half2 recurrence (C·s term small; D·u exact fp32).
// ---------------------------------------------------------------------------
__global__ __launch_bounds__(256)
void phase3_kernel(const float* __restrict__ x, const float* __restrict__ Alog,
                   const float* __restrict__ Bmat, const float* __restrict__ Cmat,
                   const float* __restrict__ Dvec, float* __restrict__ out) {
    extern __shared__ __align__(16) char sraw[];
    __half* slabD = (__half*)sraw;
    float* slabU = (float*)(sraw + DSLAB_HALVES * 2);
    const int tid = threadIdx.x;
    const int h0 = blockIdx.x * 256;
    const int h = h0 + tid;
    const int c = blockIdx.y;
    const int b = blockIdx.z;

    const uint32_t sD = (uint32_t)__cvta_generic_to_shared(slabD);
    const uint32_t sU = (uint32_t)__cvta_generic_to_shared(slabU);
    const size_t base = ((size_t)b * Tt + c * Lchunk) * Hh + h0;
    stage_two_slabs(sD, sU, g_dth + base, x + base, tid);

    __half2 A2h[Nn / 2], CBh[Nn / 2], s2[Nn / 2];
#pragma unroll
    for (int i = 0; i < 4; i++) {
        float4 av = *(const float4*)(Alog + h * Nn + i * 4);
        float4 bv = *(const float4*)(Bmat + h * Nn + i * 4);
        float4 cv = *(const float4*)(Cmat + h * Nn + i * 4);
        A2h[i*2]   = __floats2half2_rn(-expf(av.x) * 1.4426950408889634f,
                                       -expf(av.y) * 1.4426950408889634f);
        A2h[i*2+1] = __floats2half2_rn(-expf(av.z) * 1.4426950408889634f,
                                       -expf(av.w) * 1.4426950408889634f);
        CBh[i*2]   = __floats2half2_rn(bv.x * cv.x, bv.y * cv.y);
        CBh[i*2+1] = __floats2half2_rn(bv.z * cv.z, bv.w * cv.w);
    }
    {
        const __half* ip = g_sinith + ((size_t)(b * CHUNKS + c) * Nn) * Hh + h;
#pragma unroll
        for (int p = 0; p < Nn / 2; ++p)
            s2[p] = __halves2half2(ip[(size_t)(2*p) * Hh], ip[(size_t)(2*p+1) * Hh]);
    }

    const float Dh = Dvec[h];
    float* yp = out + base + tid;

    __syncthreads();

#pragma unroll 8
    for (int tt = 0; tt < Lchunk; ++tt) {
        const __half dth = slabD[tt * 256 + tid];
        const __half2 dt2 = __half2half2(dth);
        const float uv = slabU[tt * 256 + tid];
        const float du = __half2float(dth) * uv;
        const __half2 du2 = __float2half2_rn(du);
        __half2 y2 = __float2half2_rn(0.0f);
#pragma unroll
        for (int p = 0; p < Nn / 2; ++p) {
            const __half2 e2 = h2ex2(__hmul2(dt2, A2h[p]));
            s2[p] = __hfma2(e2, s2[p], du2);
            y2 = __hfma2(s2[p], CBh[p], y2);
        }
        yp[(size_t)tt * Hh] = fmaf(Dh, uv, __low2float(y2) + __high2float(y2));
    }
}

// ---------------------------------------------------------------------------
extern "C" void kernel_launch(void* const* d_in, const int* in_sizes, int n_in,
                              void* d_out, int out_size) {
    const float* x     = (const float*)d_in[0];
    const float* A_log = (const float*)d_in[1];
    const float* B_mat = (const float*)d_in[2];
    const float* C_mat = (const float*)d_in[3];
    const float* D_vec = (const float*)d_in[4];
    const float* W_dt  = (const float*)d_in[5];
    const float* b_dt  = (const float*)d_in[6];
    float* out = (float*)d_out;

    static int attr_set = 0;
    if (!attr_set) {
        cudaFuncSetAttribute(gemm_mma_kernel,
                             cudaFuncAttributeMaxDynamicSharedMemorySize, GEMM_DYN_SMEM);
        cudaFuncSetAttribute(phase1_kernel,
                             cudaFuncAttributeMaxDynamicSharedMemorySize, SLAB_BYTES_TOT);
        cudaFuncSetAttribute(phase3_kernel,
                             cudaFuncAttributeMaxDynamicSharedMemorySize, SLAB_BYTES_TOT);
        attr_set = 1;
    }

    // fp16 operand prep (x and W in one launch)
    convert_kernel<<<XB + WB, 256>>>(x, W_dt);

    // tensor-core GEMM + softplus epilogue -> g_dth (fp16)
    gemm_mma_kernel<<<dim3(Hh / GBN, Mrows / GBM), 256, GEMM_DYN_SMEM>>>(b_dt);

    // chunked scan (s~ space)
    phase1_kernel<<<dim3(Hh / 256, CHUNKS, Bb), 256, SLAB_BYTES_TOT>>>(x, A_log);

    const int write_state =
        ((size_t)out_size >= (size_t)Mrows * Hh + (size_t)Bb * Hh * Nn) ? 1 : 0;
    phase2_kernel<<<(Bb * Hh * Nn) / 256, 256>>>(A_log, B_mat, out, write_state);

    phase3_kernel<<<dim3(Hh / 256, CHUNKS, Bb), 256, SLAB_BYTES_TOT>>>(x, A_log, B_mat, C_mat, D_vec, out);
}